// round 15
// baseline (speedup 1.0000x reference)
#include <cuda_runtime.h>
#include <cstdint>

#define B_TOTAL   8192
#define LEAK      0.01f
#define BN_EPS    1e-5f

__device__ float g_conv[64 * 90 * B_TOTAL];   // conv1 out [64][10][9][B]
__device__ float g_y1[16 * 50 * B_TOTAL];
__device__ float g_y2[8 * 66 * B_TOTAL];
__device__ float g_y3[8 * 48 * B_TOTAL];
__device__ float g_part1[1600 * 32];
__device__ float g_part2[528 * 16];
__device__ float g_part3[384 * 16];
__device__ float g_bnA1[16], g_bnB1[16];
__device__ float g_bnA2[8],  g_bnB2[8];
__device__ float g_bnA3[8],  g_bnB3[8];

typedef unsigned long long u64;

__device__ __forceinline__ float lrelu(float v) { return v < 0.f ? LEAK * v : v; }
__device__ __forceinline__ float wsum(float v) {
#pragma unroll
    for (int s = 16; s; s >>= 1) v += __shfl_xor_sync(0xffffffffu, v, s);
    return v;
}
__device__ __forceinline__ u64 dup2f(float v) {
    u64 r; asm("mov.b64 %0, {%1, %1};" : "=l"(r) : "f"(v)); return r;
}
#define FMA2(d, a, b)   asm("fma.rn.f32x2 %0, %1, %2, %0;" : "+l"(d) : "l"(a), "l"(b))
#define UNPK(lo, hi, v) asm("mov.b64 {%0, %1}, %2;" : "=f"(lo), "=f"(hi) : "l"(v))

#define CH8(ar, s)                                              \
    FMA2(ar[0], s, wA.x); FMA2(ar[1], s, wA.y);                 \
    FMA2(ar[2], s, wB.x); FMA2(ar[3], s, wB.y);                 \
    FMA2(ar[4], s, wC.x); FMA2(ar[5], s, wC.y);                 \
    FMA2(ar[6], s, wD.x); FMA2(ar[7], s, wD.y);

// ============================ K0: conv1 + lrelu ===============================
#define SMEM0 ((256 * 91 + 32 + 8) * 4)
__global__ void k0_conv1(const float* __restrict__ img,
                         const float* __restrict__ w1,
                         const float* __restrict__ b1) {
    extern __shared__ float sm0[];
    float* simg = sm0;
    float* sw   = sm0 + 256 * 91;
    float* sb   = sw + 32;
    const int t  = threadIdx.x;
    const int B0 = blockIdx.x * 256;
    const int c0 = blockIdx.y * 8;

#pragma unroll 1
    for (int i = 0; i < 90; ++i) {
        int f = i * 256 + t;
        int s = f / 90, off = f - s * 90;
        simg[s * 91 + off] = img[(B0 + s) * 90 + off];
    }
    if (t < 32) sw[t] = w1[c0 * 4 + t];
    if (t < 8)  sb[t] = b1[c0 + t];
    __syncthreads();

    const int q  = t & 63;
    const int cg = t >> 6;
    float W00[2], W01[2], W10[2], W11[2], BB[2];
#pragma unroll
    for (int c2 = 0; c2 < 2; ++c2) {
        int cc = cg * 2 + c2;
        W00[c2] = sw[cc * 4 + 0]; W01[c2] = sw[cc * 4 + 1];
        W10[c2] = sw[cc * 4 + 2]; W11[c2] = sw[cc * 4 + 3];
        BB[c2]  = sb[cc];
    }

#pragma unroll 1
    for (int h = 0; h < 10; ++h) {
        float a[4][9], b[4][9];
        const bool hb = (h < 9);
#pragma unroll
        for (int s = 0; s < 4; ++s) {
            const float* rp = simg + (q * 4 + s) * 91 + h * 9;
#pragma unroll
            for (int w = 0; w < 9; ++w) {
                a[s][w] = rp[w];
                b[s][w] = hb ? rp[9 + w] : 0.f;
            }
        }
#pragma unroll
        for (int c2 = 0; c2 < 2; ++c2) {
            const int c = c0 + cg * 2 + c2;
            float* op = g_conv + ((size_t)c * 90 + h * 9) * B_TOTAL + B0 + q * 4;
            const float w00 = W00[c2], w01 = W01[c2], w10 = W10[c2], w11 = W11[c2], bv = BB[c2];
#pragma unroll
            for (int w = 0; w < 9; ++w) {
                float v[4];
#pragma unroll
                for (int s = 0; s < 4; ++s) {
                    float t0 = fmaf(a[s][w], w00, bv);
                    if (w < 8) t0 = fmaf(a[s][w + 1], w01, t0);
                    t0 = fmaf(b[s][w], w10, t0);
                    if (w < 8) t0 = fmaf(b[s][w + 1], w11, t0);
                    v[s] = lrelu(t0);
                }
                ((float4*)(op + (size_t)w * B_TOTAL))[0] = make_float4(v[0], v[1], v[2], v[3]);
            }
        }
    }
}

// ============================ K1: LC1 compacted, L2-resident tiles ============
// grid (50, 32), block 256. Thread: 1 sample x 16 ch. NV = NIJ*64. Prefetch 8.
#define K1_BODY(PF, KIDX) do {                                               \
    float cur = PF;                                                          \
    PF = gA[soff[(KIDX) + 8]];                                               \
    u64 s0 = dup2f(cur);                                                     \
    const ulonglong2* wp = Wv + (size_t)(KIDX) * 4;                          \
    ulonglong2 wA = wp[0], wB = wp[1], wC = wp[2], wD = wp[3];               \
    CH8(acc, s0);                                                            \
} while (0)

template<int NIJ>
__device__ __forceinline__ void k1_body(
    int t, int loc, int h, int w, int B0, int by,
    const float* __restrict__ lcw, const float* __restrict__ lcb,
    float* Wsm, int* soff, float* red, int* smi, int* smj) {
    constexpr int NV = NIJ * 64;

    const int i3lo = (h == 0) ? 1 : 0;
    const int j3lo = (w == 0) ? 1 : 0;
    const int nJ = (w == 0 || w == 4) ? 2 : 3;
    if (t < NIJ) { smi[t] = i3lo + t / nJ; smj[t] = j3lo + t - (t / nJ) * nJ; }
    if (t < 32) red[t] = 0.f;
    __syncthreads();

#pragma unroll
    for (int rr = 0; rr < 4; ++rr) {
        int rid = rr * 256 + t;
        int o = rid >> 6, c = rid & 63;
        const float* src = lcw + ((size_t)(o * 64 + c) * 50 + loc) * 9;
#pragma unroll
        for (int m = 0; m < NIJ; ++m)
            Wsm[((m << 6) + c) * 16 + o] = src[smi[m] * 3 + smj[m]];
    }
    for (int kk = t; kk < NV + 8; kk += 256) {
        int v = 0;
        if (kk < NV) {
            int c = kk & 63, m = kk >> 6;
            v = ((c * 10 + h + smi[m] - 1) * 9 + (2 * w + smj[m] - 1)) * B_TOTAL;
        }
        soff[kk] = v;
    }
    __syncthreads();

    const float* gA = g_conv + B0 + t;
    const ulonglong2* Wv = (const ulonglong2*)Wsm;
    u64 acc[8] = {};

    float pf0 = gA[soff[0]], pf1 = gA[soff[1]], pf2 = gA[soff[2]], pf3 = gA[soff[3]];
    float pf4 = gA[soff[4]], pf5 = gA[soff[5]], pf6 = gA[soff[6]], pf7 = gA[soff[7]];

#pragma unroll 2
    for (int k = 0; k < NV; k += 8) {
        K1_BODY(pf0, k);
        K1_BODY(pf1, k + 1);
        K1_BODY(pf2, k + 2);
        K1_BODY(pf3, k + 3);
        K1_BODY(pf4, k + 4);
        K1_BODY(pf5, k + 5);
        K1_BODY(pf6, k + 6);
        K1_BODY(pf7, k + 7);
    }

#pragma unroll
    for (int j = 0; j < 8; ++j) {
        const int o0 = 2 * j, o1 = 2 * j + 1;
        const float b0v = lcb[o0 * 50 + loc];
        const float b1v = lcb[o1 * 50 + loc];
        float v0, v1;
        UNPK(v0, v1, acc[j]);
        float a0 = lrelu(v0 + b0v);
        float c0 = lrelu(v1 + b1v);
        g_y1[((size_t)o0 * 50 + loc) * B_TOTAL + B0 + t] = a0;
        g_y1[((size_t)o1 * 50 + loc) * B_TOTAL + B0 + t] = c0;
        float s0 = wsum(a0), q0 = wsum(a0 * a0);
        float s1 = wsum(c0), q1 = wsum(c0 * c0);
        if ((t & 31) == 0) {
            atomicAdd(&red[o0 * 2 + 0], s0); atomicAdd(&red[o0 * 2 + 1], q0);
            atomicAdd(&red[o1 * 2 + 0], s1); atomicAdd(&red[o1 * 2 + 1], q1);
        }
    }
    __syncthreads();
    if (t < 32) g_part1[(by * 50 + loc) * 32 + t] = red[t];
}

__global__ void __launch_bounds__(256, 4) k1_lc1(const float* __restrict__ lcw,
                                                 const float* __restrict__ lcb) {
    __shared__ __align__(16) float Wsm[9216];
    __shared__ int soff[584];
    __shared__ float red[32];
    __shared__ int smi[9], smj[9];
    const int t   = threadIdx.x;
    const int loc = blockIdx.x;
    const int B0  = blockIdx.y * 256;
    const int h = loc / 5, w = loc - h * 5;
    const int nI = (h == 0 || h == 9) ? 2 : 3;
    const int nJ = (w == 0 || w == 4) ? 2 : 3;
    const int nIJ = nI * nJ;
    if (nIJ == 9)      k1_body<9>(t, loc, h, w, B0, blockIdx.y, lcw, lcb, Wsm, soff, red, smi, smj);
    else if (nIJ == 6) k1_body<6>(t, loc, h, w, B0, blockIdx.y, lcw, lcb, Wsm, soff, red, smi, smj);
    else               k1_body<4>(t, loc, h, w, B0, blockIdx.y, lcw, lcb, Wsm, soff, red, smi, smj);
}

// ============================ K3/K5 common body ===============================
#define LC_BODY(FA, FB, KIDX) do {                                           \
    ulonglong2 a01 = FA, a23 = FB;                                           \
    { const ulonglong2* _p = (const ulonglong2*)(gA + soff[(KIDX) + 2]);     \
      FA = _p[0]; FB = _p[1]; }                                              \
    const ulonglong2* wp = (const ulonglong2*)(Wd + (size_t)(KIDX) * 8);     \
    ulonglong2 wA = wp[0], wB = wp[1], wC = wp[2], wD = wp[3];               \
    CH8(acc[0], a01.x); CH8(acc[1], a01.y);                                  \
    CH8(acc[2], a23.x); CH8(acc[3], a23.y);                                  \
} while (0)

// ============================ K3: BN1(folded) + LC2 ===========================
template<int NIJ>
__device__ __forceinline__ void k3_body(
    int t, int loc, int h2, int w2, int B0, int by,
    const float* __restrict__ lcw, const float* __restrict__ lcb,
    u64* Wd, float* biasc, int* soff, float* red, int* smi, int* smj) {
    constexpr int NV = NIJ * 16;

    const int ilo = (h2 == 0) ? 1 : 0;
    const int jlo = (w2 == 0) ? 1 : 0;
    const int nJ = (w2 == 0 || w2 == 5) ? 1 : 2;
    if (t < NIJ) { smi[t] = ilo + t / nJ; smj[t] = jlo + t - (t / nJ) * nJ; }
    if (t < 16) red[t] = 0.f;
    __syncthreads();

#pragma unroll
    for (int ff = 0; ff < NV * 8; ff += 128) {
        int f = ff + t;
        int kk = f >> 3, o = f & 7;
        int c = kk & 15, m = kk >> 4;
        float wv = lcw[(size_t)((o * 16 + c) * 66 + loc) * 4 + smi[m] * 2 + smj[m]];
        Wd[f] = dup2f(wv * g_bnA1[c]);
    }
    for (int kk = t; kk < NV + 2; kk += 128) {
        int v = 0;
        if (kk < NV) {
            int c = kk & 15, m = kk >> 4;
            v = (c * 50 + (h2 + smi[m] - 1) * 5 + (w2 + smj[m] - 1)) * B_TOTAL;
        }
        soff[kk] = v;
    }
    if (t < 8) {
        float s = 0.f;
#pragma unroll
        for (int kk = 0; kk < NV; ++kk) {
            int c = kk & 15, m = kk >> 4;
            s += lcw[(size_t)((t * 16 + c) * 66 + loc) * 4 + smi[m] * 2 + smj[m]] * g_bnB1[c];
        }
        biasc[t] = s;
    }
    __syncthreads();

    const float* gA = g_y1 + B0 + t * 8;
    u64 acc[4][8] = {};
    ulonglong2 f0a, f0b, f1a, f1b;
    { const ulonglong2* p = (const ulonglong2*)(gA + soff[0]); f0a = p[0]; f0b = p[1]; }
    { const ulonglong2* p = (const ulonglong2*)(gA + soff[1]); f1a = p[0]; f1b = p[1]; }

#pragma unroll 4
    for (int k = 0; k < NV; k += 2) {
        LC_BODY(f0a, f0b, k);
        LC_BODY(f1a, f1b, k + 1);
    }

#pragma unroll
    for (int o = 0; o < 8; ++o) {
        const float bv = lcb[o * 66 + loc] + biasc[o];
        float v[8];
#pragma unroll
        for (int p = 0; p < 4; ++p) UNPK(v[2 * p], v[2 * p + 1], acc[p][o]);
#pragma unroll
        for (int p = 0; p < 8; ++p) v[p] = lrelu(v[p] + bv);
        float* dst = g_y2 + ((size_t)o * 66 + loc) * B_TOTAL + B0 + t * 8;
        ((float4*)dst)[0] = make_float4(v[0], v[1], v[2], v[3]);
        ((float4*)dst)[1] = make_float4(v[4], v[5], v[6], v[7]);
        float s = wsum(v[0]+v[1]+v[2]+v[3]+v[4]+v[5]+v[6]+v[7]);
        float q = wsum(v[0]*v[0]+v[1]*v[1]+v[2]*v[2]+v[3]*v[3]
                     + v[4]*v[4]+v[5]*v[5]+v[6]*v[6]+v[7]*v[7]);
        if ((t & 31) == 0) {
            atomicAdd(&red[o * 2 + 0], s);
            atomicAdd(&red[o * 2 + 1], q);
        }
    }
    __syncthreads();
    if (t < 16) g_part2[(by * 66 + loc) * 16 + t] = red[t];
}

__global__ void __launch_bounds__(128, 4) k3_lc2(const float* __restrict__ lcw,
                                                 const float* __restrict__ lcb) {
    __shared__ __align__(16) u64 Wd[512];
    __shared__ float biasc[8];
    __shared__ int soff[66];
    __shared__ float red[16];
    __shared__ int smi[4], smj[4];
    const int t   = threadIdx.x;
    const int loc = blockIdx.x;
    const int B0  = blockIdx.y * 1024;
    const int h2 = loc / 6, w2 = loc - h2 * 6;
    const int nI = (h2 == 0 || h2 == 10) ? 1 : 2;
    const int nJ = (w2 == 0 || w2 == 5) ? 1 : 2;
    const int nIJ = nI * nJ;
    if (nIJ == 4)      k3_body<4>(t, loc, h2, w2, B0, blockIdx.y, lcw, lcb, Wd, biasc, soff, red, smi, smj);
    else if (nIJ == 2) k3_body<2>(t, loc, h2, w2, B0, blockIdx.y, lcw, lcb, Wd, biasc, soff, red, smi, smj);
    else               k3_body<1>(t, loc, h2, w2, B0, blockIdx.y, lcw, lcb, Wd, biasc, soff, red, smi, smj);
}

// ============================ K5: BN2(folded) + LC3 ===========================
template<int NIJ>
__device__ __forceinline__ void k5_body(
    int t, int loc, int h3, int w3, int B0, int by,
    const float* __restrict__ lcw, const float* __restrict__ lcb,
    u64* Wd, float* biasc, int* soff, float* red, int* smi, int* smj) {
    constexpr int NV = NIJ * 8;

    const int ilo = (h3 == 0) ? 1 : 0;
    const int jlo = (w3 == 0) ? 1 : 0;
    const int nJ = (w3 == 0 || w3 == 3) ? 1 : 2;
    if (t < NIJ) { smi[t] = ilo + t / nJ; smj[t] = jlo + t - (t / nJ) * nJ; }
    if (t < 16) red[t] = 0.f;
    __syncthreads();

    {
        int f = t;
        if (f < NV * 8) {
            int kk = f >> 3, o = f & 7;
            int c = kk & 7, m = kk >> 3;
            float wv = lcw[(size_t)((o * 8 + c) * 48 + loc) * 4 + smi[m] * 2 + smj[m]];
            Wd[f] = dup2f(wv * g_bnA2[c]);
        }
        if (NV * 8 > 128) {
            f = 128 + t;
            if (f < NV * 8) {
                int kk = f >> 3, o = f & 7;
                int c = kk & 7, m = kk >> 3;
                float wv = lcw[(size_t)((o * 8 + c) * 48 + loc) * 4 + smi[m] * 2 + smj[m]];
                Wd[f] = dup2f(wv * g_bnA2[c]);
            }
        }
    }
    for (int kk = t; kk < NV + 2; kk += 128) {
        int v = 0;
        if (kk < NV) {
            int c = kk & 7, m = kk >> 3;
            v = (c * 66 + (h3 + smi[m] - 1) * 6 + (2 * w3 + smj[m] - 1)) * B_TOTAL;
        }
        soff[kk] = v;
    }
    if (t < 8) {
        float s = 0.f;
#pragma unroll
        for (int kk = 0; kk < NV; ++kk) {
            int c = kk & 7, m = kk >> 3;
            s += lcw[(size_t)((t * 8 + c) * 48 + loc) * 4 + smi[m] * 2 + smj[m]] * g_bnB2[c];
        }
        biasc[t] = s;
    }
    __syncthreads();

    const float* gA = g_y2 + B0 + t * 8;
    u64 acc[4][8] = {};
    ulonglong2 f0a, f0b, f1a, f1b;
    { const ulonglong2* p = (const ulonglong2*)(gA + soff[0]); f0a = p[0]; f0b = p[1]; }
    { const ulonglong2* p = (const ulonglong2*)(gA + soff[1]); f1a = p[0]; f1b = p[1]; }

#pragma unroll 4
    for (int k = 0; k < NV; k += 2) {
        LC_BODY(f0a, f0b, k);
        LC_BODY(f1a, f1b, k + 1);
    }

#pragma unroll
    for (int o = 0; o < 8; ++o) {
        const float bv = lcb[o * 48 + loc] + biasc[o];
        float v[8];
#pragma unroll
        for (int p = 0; p < 4; ++p) UNPK(v[2 * p], v[2 * p + 1], acc[p][o]);
#pragma unroll
        for (int p = 0; p < 8; ++p) v[p] = lrelu(v[p] + bv);
        float* dst = g_y3 + ((size_t)o * 48 + loc) * B_TOTAL + B0 + t * 8;
        ((float4*)dst)[0] = make_float4(v[0], v[1], v[2], v[3]);
        ((float4*)dst)[1] = make_float4(v[4], v[5], v[6], v[7]);
        float s = wsum(v[0]+v[1]+v[2]+v[3]+v[4]+v[5]+v[6]+v[7]);
        float q = wsum(v[0]*v[0]+v[1]*v[1]+v[2]*v[2]+v[3]*v[3]
                     + v[4]*v[4]+v[5]*v[5]+v[6]*v[6]+v[7]*v[7]);
        if ((t & 31) == 0) {
            atomicAdd(&red[o * 2 + 0], s);
            atomicAdd(&red[o * 2 + 1], q);
        }
    }
    __syncthreads();
    if (t < 16) g_part3[(by * 48 + loc) * 16 + t] = red[t];
}

__global__ void __launch_bounds__(128, 4) k5_lc3(const float* __restrict__ lcw,
                                                 const float* __restrict__ lcb) {
    __shared__ __align__(16) u64 Wd[256];
    __shared__ float biasc[8];
    __shared__ int soff[34];
    __shared__ float red[16];
    __shared__ int smi[4], smj[4];
    const int t   = threadIdx.x;
    const int loc = blockIdx.x;
    const int B0  = blockIdx.y * 1024;
    const int h3 = loc >> 2, w3 = loc & 3;
    const int nI = (h3 == 0 || h3 == 11) ? 1 : 2;
    const int nJ = (w3 == 0 || w3 == 3) ? 1 : 2;
    const int nIJ = nI * nJ;
    if (nIJ == 4)      k5_body<4>(t, loc, h3, w3, B0, blockIdx.y, lcw, lcb, Wd, biasc, soff, red, smi, smj);
    else if (nIJ == 2) k5_body<2>(t, loc, h3, w3, B0, blockIdx.y, lcw, lcb, Wd, biasc, soff, red, smi, smj);
    else               k5_body<1>(t, loc, h3, w3, B0, blockIdx.y, lcw, lcb, Wd, biasc, soff, red, smi, smj);
}

// ============================ stat reducer ====================================
__global__ void kred(int stage, int nb, int nch, float invN,
                     const float* __restrict__ gamma, const float* __restrict__ beta) {
    __shared__ float sm[1024];
    const float* part = (stage == 0) ? g_part1 : (stage == 1) ? g_part2 : g_part3;
    float* bnA = (stage == 0) ? g_bnA1 : (stage == 1) ? g_bnA2 : g_bnA3;
    float* bnB = (stage == 0) ? g_bnB1 : (stage == 1) ? g_bnB2 : g_bnB3;
    const int t = threadIdx.x;
    const int slots = 2 * nch;
    const int grp = t % slots;
    const int lane = t / slots;
    const int per = blockDim.x / slots;
    float s = 0.f;
    for (int i = lane; i < nb; i += per) s += part[i * slots + grp];
    sm[t] = s;
    __syncthreads();
    for (int step = per >> 1; step > 0; step >>= 1) {
        if (lane < step) sm[t] += sm[t + step * slots];
        __syncthreads();
    }
    if (t < nch) {
        float sum = sm[t * 2 + 0], sq = sm[t * 2 + 1];
        float mean = sum * invN;
        float var = sq * invN - mean * mean;
        float rs = rsqrtf(var + BN_EPS);
        float g = gamma[t];
        bnA[t] = g * rs;
        bnB[t] = beta[t] - mean * g * rs;
    }
}

// ============================ K7: BN3 + transpose to output ===================
__global__ void k7_out(float* __restrict__ out) {
    __shared__ float tile[32][65];
    __shared__ float a3[8], b3[8];
    const int t  = threadIdx.x;
    const int f0 = blockIdx.x * 32;
    const int b0 = blockIdx.y * 64;
    if (t < 8) { a3[t] = g_bnA3[t]; b3[t] = g_bnB3[t]; }
    __syncthreads();
#pragma unroll
    for (int r = 0; r < 8; ++r) {
        int f = r * 4 + (t >> 6);
        int b = t & 63;
        float v = g_y3[(size_t)(f0 + f) * B_TOTAL + b0 + b];
        int c = (f0 + f) / 48;
        tile[f][b] = fmaf(a3[c], v, b3[c]);
    }
    __syncthreads();
#pragma unroll
    for (int r = 0; r < 8; ++r) {
        int f = t & 31;
        int b = r * 8 + (t >> 5);
        out[(size_t)(b0 + b) * 384 + f0 + f] = tile[f][b];
    }
}

// ============================ launch ==========================================
extern "C" void kernel_launch(void* const* d_in, const int* in_sizes, int n_in,
                              void* d_out, int out_size) {
    const float* image = (const float*)d_in[0];
    const float* c1w   = (const float*)d_in[1];
    const float* c1b   = (const float*)d_in[2];
    const float* lc1w  = (const float*)d_in[3];
    const float* lc1b  = (const float*)d_in[4];
    const float* lc2w  = (const float*)d_in[5];
    const float* lc2b  = (const float*)d_in[6];
    const float* lc3w  = (const float*)d_in[7];
    const float* lc3b  = (const float*)d_in[8];
    const float* g1    = (const float*)d_in[9];
    const float* be1   = (const float*)d_in[10];
    const float* g2    = (const float*)d_in[11];
    const float* be2   = (const float*)d_in[12];
    const float* g3    = (const float*)d_in[13];
    const float* be3   = (const float*)d_in[14];
    float* out = (float*)d_out;

    cudaFuncSetAttribute(k0_conv1, cudaFuncAttributeMaxDynamicSharedMemorySize, SMEM0);

    k0_conv1<<<dim3(32, 8),  256, SMEM0>>>(image, c1w, c1b);
    k1_lc1  <<<dim3(50, 32), 256>>>(lc1w, lc1b);
    kred    <<<1, 1024>>>(0, 1600, 16, 1.0f / (8192.0f * 50.0f), g1, be1);
    k3_lc2  <<<dim3(66, 8),  128>>>(lc2w, lc2b);
    kred    <<<1, 1024>>>(1, 528, 8, 1.0f / (8192.0f * 66.0f), g2, be2);
    k5_lc3  <<<dim3(48, 8),  128>>>(lc3w, lc3b);
    kred    <<<1, 1024>>>(2, 384, 8, 1.0f / (8192.0f * 48.0f), g3, be3);
    k7_out  <<<dim3(12, 128), 256>>>(out);
}

// round 16
// speedup vs baseline: 1.2106x; 1.2106x over previous
#include <cuda_runtime.h>
#include <cstdint>

#define B_TOTAL   8192
#define LEAK      0.01f
#define BN_EPS    1e-5f

__device__ float g_conv[64 * 90 * B_TOTAL];   // conv1 out [64][10][9][B]
__device__ float g_pacc[16 * 50 * B_TOTAL];   // k1 pass-0 partial sums
__device__ float g_y1[16 * 50 * B_TOTAL];
__device__ float g_y2[8 * 66 * B_TOTAL];
__device__ float g_y3[8 * 48 * B_TOTAL];
__device__ float g_part1[400 * 32];
__device__ float g_part2[528 * 16];
__device__ float g_part3[384 * 16];
__device__ float g_bnA1[16], g_bnB1[16];
__device__ float g_bnA2[8],  g_bnB2[8];
__device__ float g_bnA3[8],  g_bnB3[8];

typedef unsigned long long u64;

__device__ __forceinline__ float lrelu(float v) { return v < 0.f ? LEAK * v : v; }
__device__ __forceinline__ float wsum(float v) {
#pragma unroll
    for (int s = 16; s; s >>= 1) v += __shfl_xor_sync(0xffffffffu, v, s);
    return v;
}
__device__ __forceinline__ u64 dup2f(float v) {
    u64 r; asm("mov.b64 %0, {%1, %1};" : "=l"(r) : "f"(v)); return r;
}
#define FMA2(d, a, b)   asm("fma.rn.f32x2 %0, %1, %2, %0;" : "+l"(d) : "l"(a), "l"(b))
#define UNPK(lo, hi, v) asm("mov.b64 {%0, %1}, %2;" : "=f"(lo), "=f"(hi) : "l"(v))

#define CH8(ar, s)                                              \
    FMA2(ar[0], s, wA.x); FMA2(ar[1], s, wA.y);                 \
    FMA2(ar[2], s, wB.x); FMA2(ar[3], s, wB.y);                 \
    FMA2(ar[4], s, wC.x); FMA2(ar[5], s, wC.y);                 \
    FMA2(ar[6], s, wD.x); FMA2(ar[7], s, wD.y);

// ============================ K0: conv1 + lrelu ===============================
#define SMEM0 ((256 * 91 + 32 + 8) * 4)
__global__ void k0_conv1(const float* __restrict__ img,
                         const float* __restrict__ w1,
                         const float* __restrict__ b1) {
    extern __shared__ float sm0[];
    float* simg = sm0;
    float* sw   = sm0 + 256 * 91;
    float* sb   = sw + 32;
    const int t  = threadIdx.x;
    const int B0 = blockIdx.x * 256;
    const int c0 = blockIdx.y * 8;

#pragma unroll 1
    for (int i = 0; i < 90; ++i) {
        int f = i * 256 + t;
        int s = f / 90, off = f - s * 90;
        simg[s * 91 + off] = img[(B0 + s) * 90 + off];
    }
    if (t < 32) sw[t] = w1[c0 * 4 + t];
    if (t < 8)  sb[t] = b1[c0 + t];
    __syncthreads();

    const int q  = t & 63;
    const int cg = t >> 6;
    float W00[2], W01[2], W10[2], W11[2], BB[2];
#pragma unroll
    for (int c2 = 0; c2 < 2; ++c2) {
        int cc = cg * 2 + c2;
        W00[c2] = sw[cc * 4 + 0]; W01[c2] = sw[cc * 4 + 1];
        W10[c2] = sw[cc * 4 + 2]; W11[c2] = sw[cc * 4 + 3];
        BB[c2]  = sb[cc];
    }

#pragma unroll 1
    for (int h = 0; h < 10; ++h) {
        float a[4][9], b[4][9];
        const bool hb = (h < 9);
#pragma unroll
        for (int s = 0; s < 4; ++s) {
            const float* rp = simg + (q * 4 + s) * 91 + h * 9;
#pragma unroll
            for (int w = 0; w < 9; ++w) {
                a[s][w] = rp[w];
                b[s][w] = hb ? rp[9 + w] : 0.f;
            }
        }
#pragma unroll
        for (int c2 = 0; c2 < 2; ++c2) {
            const int c = c0 + cg * 2 + c2;
            float* op = g_conv + ((size_t)c * 90 + h * 9) * B_TOTAL + B0 + q * 4;
            const float w00 = W00[c2], w01 = W01[c2], w10 = W10[c2], w11 = W11[c2], bv = BB[c2];
#pragma unroll
            for (int w = 0; w < 9; ++w) {
                float v[4];
#pragma unroll
                for (int s = 0; s < 4; ++s) {
                    float t0 = fmaf(a[s][w], w00, bv);
                    if (w < 8) t0 = fmaf(a[s][w + 1], w01, t0);
                    t0 = fmaf(b[s][w], w10, t0);
                    if (w < 8) t0 = fmaf(b[s][w + 1], w11, t0);
                    v[s] = lrelu(t0);
                }
                ((float4*)(op + (size_t)w * B_TOTAL))[0] = make_float4(v[0], v[1], v[2], v[3]);
            }
        }
    }
}

// ============================ K1: LC1 compacted, 2-pass K-split ===============
// Thread: 4 samples x 16 ch. NV = NIJ*64. Pass 0: kk<NV/2 -> raw partials.
// Pass 1: kk>=NV/2 + partial + bias + lrelu + stats. Both passes L2-resident.
#define K1_BODY(PF, KIDX) do {                                               \
    float4 cur = PF;                                                         \
    PF = *(const float4*)(gA + soff[(KIDX) + 8]);                            \
    u64 s0 = dup2f(cur.x), s1 = dup2f(cur.y);                                \
    u64 s2 = dup2f(cur.z), s3 = dup2f(cur.w);                                \
    const ulonglong2* wp = Wv + (size_t)(KIDX) * 4;                          \
    ulonglong2 wA = wp[0], wB = wp[1], wC = wp[2], wD = wp[3];               \
    CH8(acc[0], s0); CH8(acc[1], s1); CH8(acc[2], s2); CH8(acc[3], s3);      \
} while (0)

template<int NIJ, int PASS>
__device__ __forceinline__ void k1_body(
    int t, int loc, int h, int w, int B0, int by,
    const float* __restrict__ lcw, const float* __restrict__ lcb,
    float* Wsm, int* soff, float* red, int* smi, int* smj) {
    constexpr int NV   = NIJ * 64;
    constexpr int KMID = NV / 2;            // 128/192/288, all % 8 == 0
    constexpr int KBEG = PASS ? KMID : 0;
    constexpr int KEND = PASS ? NV : KMID;

    const int i3lo = (h == 0) ? 1 : 0;
    const int j3lo = (w == 0) ? 1 : 0;
    const int nJ = (w == 0 || w == 4) ? 2 : 3;
    if (t < NIJ) { smi[t] = i3lo + t / nJ; smj[t] = j3lo + t - (t / nJ) * nJ; }
    if (t < 32) red[t] = 0.f;
    __syncthreads();

#pragma unroll
    for (int rr = 0; rr < 4; ++rr) {
        int rid = rr * 256 + t;
        int o = rid >> 6, c = rid & 63;
        const float* src = lcw + ((size_t)(o * 64 + c) * 50 + loc) * 9;
#pragma unroll
        for (int m = 0; m < NIJ; ++m)
            Wsm[((m << 6) + c) * 16 + o] = src[smi[m] * 3 + smj[m]];
    }
    for (int kk = t; kk < NV + 8; kk += 256) {
        int v = 0;
        if (kk < NV) {
            int c = kk & 63, m = kk >> 6;
            v = ((c * 10 + h + smi[m] - 1) * 9 + (2 * w + smj[m] - 1)) * B_TOTAL;
        }
        soff[kk] = v;
    }
    __syncthreads();

    const float* gA = g_conv + B0 + t * 4;
    const ulonglong2* Wv = (const ulonglong2*)Wsm;
    u64 acc[4][8] = {};

    float4 pf0 = *(const float4*)(gA + soff[KBEG + 0]);
    float4 pf1 = *(const float4*)(gA + soff[KBEG + 1]);
    float4 pf2 = *(const float4*)(gA + soff[KBEG + 2]);
    float4 pf3 = *(const float4*)(gA + soff[KBEG + 3]);
    float4 pf4 = *(const float4*)(gA + soff[KBEG + 4]);
    float4 pf5 = *(const float4*)(gA + soff[KBEG + 5]);
    float4 pf6 = *(const float4*)(gA + soff[KBEG + 6]);
    float4 pf7 = *(const float4*)(gA + soff[KBEG + 7]);

#pragma unroll 2
    for (int k = KBEG; k < KEND; k += 8) {
        K1_BODY(pf0, k);
        K1_BODY(pf1, k + 1);
        K1_BODY(pf2, k + 2);
        K1_BODY(pf3, k + 3);
        K1_BODY(pf4, k + 4);
        K1_BODY(pf5, k + 5);
        K1_BODY(pf6, k + 6);
        K1_BODY(pf7, k + 7);
    }

    if (PASS == 0) {
        // store raw partials (no bias / lrelu / stats)
#pragma unroll
        for (int j = 0; j < 8; ++j) {
            const int o0 = 2 * j, o1 = 2 * j + 1;
            float lo[4], hi[4];
#pragma unroll
            for (int s = 0; s < 4; ++s) UNPK(lo[s], hi[s], acc[s][j]);
            ((float4*)(g_pacc + ((size_t)o0 * 50 + loc) * B_TOTAL + B0))[t] =
                make_float4(lo[0], lo[1], lo[2], lo[3]);
            ((float4*)(g_pacc + ((size_t)o1 * 50 + loc) * B_TOTAL + B0))[t] =
                make_float4(hi[0], hi[1], hi[2], hi[3]);
        }
        return;
    }

#pragma unroll
    for (int j = 0; j < 8; ++j) {
        const int o0 = 2 * j, o1 = 2 * j + 1;
        const float b0v = lcb[o0 * 50 + loc];
        const float b1v = lcb[o1 * 50 + loc];
        float lo[4], hi[4];
#pragma unroll
        for (int s = 0; s < 4; ++s) UNPK(lo[s], hi[s], acc[s][j]);
        float4 p0 = ((const float4*)(g_pacc + ((size_t)o0 * 50 + loc) * B_TOTAL + B0))[t];
        float4 p1 = ((const float4*)(g_pacc + ((size_t)o1 * 50 + loc) * B_TOTAL + B0))[t];
        float a0 = lrelu(lo[0] + p0.x + b0v), a1 = lrelu(lo[1] + p0.y + b0v);
        float a2 = lrelu(lo[2] + p0.z + b0v), a3 = lrelu(lo[3] + p0.w + b0v);
        float c0 = lrelu(hi[0] + p1.x + b1v), c1 = lrelu(hi[1] + p1.y + b1v);
        float c2 = lrelu(hi[2] + p1.z + b1v), c3 = lrelu(hi[3] + p1.w + b1v);
        ((float4*)(g_y1 + ((size_t)o0 * 50 + loc) * B_TOTAL + B0))[t] = make_float4(a0, a1, a2, a3);
        ((float4*)(g_y1 + ((size_t)o1 * 50 + loc) * B_TOTAL + B0))[t] = make_float4(c0, c1, c2, c3);
        float s0 = wsum(a0 + a1 + a2 + a3), q0 = wsum(a0*a0 + a1*a1 + a2*a2 + a3*a3);
        float s1 = wsum(c0 + c1 + c2 + c3), q1 = wsum(c0*c0 + c1*c1 + c2*c2 + c3*c3);
        if ((t & 31) == 0) {
            atomicAdd(&red[o0 * 2 + 0], s0); atomicAdd(&red[o0 * 2 + 1], q0);
            atomicAdd(&red[o1 * 2 + 0], s1); atomicAdd(&red[o1 * 2 + 1], q1);
        }
    }
    __syncthreads();
    if (t < 32) g_part1[(by * 50 + loc) * 32 + t] = red[t];
}

template<int PASS>
__global__ void __launch_bounds__(256, 2) k1_lc1(const float* __restrict__ lcw,
                                                 const float* __restrict__ lcb) {
    __shared__ __align__(16) float Wsm[9216];
    __shared__ int soff[584];
    __shared__ float red[32];
    __shared__ int smi[9], smj[9];
    const int t   = threadIdx.x;
    const int loc = blockIdx.x;
    const int B0  = blockIdx.y * 1024;
    const int h = loc / 5, w = loc - h * 5;
    const int nI = (h == 0 || h == 9) ? 2 : 3;
    const int nJ = (w == 0 || w == 4) ? 2 : 3;
    const int nIJ = nI * nJ;
    if (nIJ == 9)      k1_body<9, PASS>(t, loc, h, w, B0, blockIdx.y, lcw, lcb, Wsm, soff, red, smi, smj);
    else if (nIJ == 6) k1_body<6, PASS>(t, loc, h, w, B0, blockIdx.y, lcw, lcb, Wsm, soff, red, smi, smj);
    else               k1_body<4, PASS>(t, loc, h, w, B0, blockIdx.y, lcw, lcb, Wsm, soff, red, smi, smj);
}

// ============================ K3/K5 common body ===============================
#define LC_BODY(FA, FB, KIDX) do {                                           \
    ulonglong2 a01 = FA, a23 = FB;                                           \
    { const ulonglong2* _p = (const ulonglong2*)(gA + soff[(KIDX) + 2]);     \
      FA = _p[0]; FB = _p[1]; }                                              \
    const ulonglong2* wp = (const ulonglong2*)(Wd + (size_t)(KIDX) * 8);     \
    ulonglong2 wA = wp[0], wB = wp[1], wC = wp[2], wD = wp[3];               \
    CH8(acc[0], a01.x); CH8(acc[1], a01.y);                                  \
    CH8(acc[2], a23.x); CH8(acc[3], a23.y);                                  \
} while (0)

// ============================ K3: BN1(folded) + LC2 ===========================
template<int NIJ>
__device__ __forceinline__ void k3_body(
    int t, int loc, int h2, int w2, int B0, int by,
    const float* __restrict__ lcw, const float* __restrict__ lcb,
    u64* Wd, float* biasc, int* soff, float* red, int* smi, int* smj) {
    constexpr int NV = NIJ * 16;

    const int ilo = (h2 == 0) ? 1 : 0;
    const int jlo = (w2 == 0) ? 1 : 0;
    const int nJ = (w2 == 0 || w2 == 5) ? 1 : 2;
    if (t < NIJ) { smi[t] = ilo + t / nJ; smj[t] = jlo + t - (t / nJ) * nJ; }
    if (t < 16) red[t] = 0.f;
    __syncthreads();

#pragma unroll
    for (int ff = 0; ff < NV * 8; ff += 128) {
        int f = ff + t;
        int kk = f >> 3, o = f & 7;
        int c = kk & 15, m = kk >> 4;
        float wv = lcw[(size_t)((o * 16 + c) * 66 + loc) * 4 + smi[m] * 2 + smj[m]];
        Wd[f] = dup2f(wv * g_bnA1[c]);
    }
    for (int kk = t; kk < NV + 2; kk += 128) {
        int v = 0;
        if (kk < NV) {
            int c = kk & 15, m = kk >> 4;
            v = (c * 50 + (h2 + smi[m] - 1) * 5 + (w2 + smj[m] - 1)) * B_TOTAL;
        }
        soff[kk] = v;
    }
    if (t < 8) {
        float s = 0.f;
#pragma unroll
        for (int kk = 0; kk < NV; ++kk) {
            int c = kk & 15, m = kk >> 4;
            s += lcw[(size_t)((t * 16 + c) * 66 + loc) * 4 + smi[m] * 2 + smj[m]] * g_bnB1[c];
        }
        biasc[t] = s;
    }
    __syncthreads();

    const float* gA = g_y1 + B0 + t * 8;
    u64 acc[4][8] = {};
    ulonglong2 f0a, f0b, f1a, f1b;
    { const ulonglong2* p = (const ulonglong2*)(gA + soff[0]); f0a = p[0]; f0b = p[1]; }
    { const ulonglong2* p = (const ulonglong2*)(gA + soff[1]); f1a = p[0]; f1b = p[1]; }

#pragma unroll 4
    for (int k = 0; k < NV; k += 2) {
        LC_BODY(f0a, f0b, k);
        LC_BODY(f1a, f1b, k + 1);
    }

#pragma unroll
    for (int o = 0; o < 8; ++o) {
        const float bv = lcb[o * 66 + loc] + biasc[o];
        float v[8];
#pragma unroll
        for (int p = 0; p < 4; ++p) UNPK(v[2 * p], v[2 * p + 1], acc[p][o]);
#pragma unroll
        for (int p = 0; p < 8; ++p) v[p] = lrelu(v[p] + bv);
        float* dst = g_y2 + ((size_t)o * 66 + loc) * B_TOTAL + B0 + t * 8;
        ((float4*)dst)[0] = make_float4(v[0], v[1], v[2], v[3]);
        ((float4*)dst)[1] = make_float4(v[4], v[5], v[6], v[7]);
        float s = wsum(v[0]+v[1]+v[2]+v[3]+v[4]+v[5]+v[6]+v[7]);
        float q = wsum(v[0]*v[0]+v[1]*v[1]+v[2]*v[2]+v[3]*v[3]
                     + v[4]*v[4]+v[5]*v[5]+v[6]*v[6]+v[7]*v[7]);
        if ((t & 31) == 0) {
            atomicAdd(&red[o * 2 + 0], s);
            atomicAdd(&red[o * 2 + 1], q);
        }
    }
    __syncthreads();
    if (t < 16) g_part2[(by * 66 + loc) * 16 + t] = red[t];
}

__global__ void __launch_bounds__(128, 4) k3_lc2(const float* __restrict__ lcw,
                                                 const float* __restrict__ lcb) {
    __shared__ __align__(16) u64 Wd[512];
    __shared__ float biasc[8];
    __shared__ int soff[66];
    __shared__ float red[16];
    __shared__ int smi[4], smj[4];
    const int t   = threadIdx.x;
    const int loc = blockIdx.x;
    const int B0  = blockIdx.y * 1024;
    const int h2 = loc / 6, w2 = loc - h2 * 6;
    const int nI = (h2 == 0 || h2 == 10) ? 1 : 2;
    const int nJ = (w2 == 0 || w2 == 5) ? 1 : 2;
    const int nIJ = nI * nJ;
    if (nIJ == 4)      k3_body<4>(t, loc, h2, w2, B0, blockIdx.y, lcw, lcb, Wd, biasc, soff, red, smi, smj);
    else if (nIJ == 2) k3_body<2>(t, loc, h2, w2, B0, blockIdx.y, lcw, lcb, Wd, biasc, soff, red, smi, smj);
    else               k3_body<1>(t, loc, h2, w2, B0, blockIdx.y, lcw, lcb, Wd, biasc, soff, red, smi, smj);
}

// ============================ K5: BN2(folded) + LC3 ===========================
template<int NIJ>
__device__ __forceinline__ void k5_body(
    int t, int loc, int h3, int w3, int B0, int by,
    const float* __restrict__ lcw, const float* __restrict__ lcb,
    u64* Wd, float* biasc, int* soff, float* red, int* smi, int* smj) {
    constexpr int NV = NIJ * 8;

    const int ilo = (h3 == 0) ? 1 : 0;
    const int jlo = (w3 == 0) ? 1 : 0;
    const int nJ = (w3 == 0 || w3 == 3) ? 1 : 2;
    if (t < NIJ) { smi[t] = ilo + t / nJ; smj[t] = jlo + t - (t / nJ) * nJ; }
    if (t < 16) red[t] = 0.f;
    __syncthreads();

    {
        int f = t;
        if (f < NV * 8) {
            int kk = f >> 3, o = f & 7;
            int c = kk & 7, m = kk >> 3;
            float wv = lcw[(size_t)((o * 8 + c) * 48 + loc) * 4 + smi[m] * 2 + smj[m]];
            Wd[f] = dup2f(wv * g_bnA2[c]);
        }
        if (NV * 8 > 128) {
            f = 128 + t;
            if (f < NV * 8) {
                int kk = f >> 3, o = f & 7;
                int c = kk & 7, m = kk >> 3;
                float wv = lcw[(size_t)((o * 8 + c) * 48 + loc) * 4 + smi[m] * 2 + smj[m]];
                Wd[f] = dup2f(wv * g_bnA2[c]);
            }
        }
    }
    for (int kk = t; kk < NV + 2; kk += 128) {
        int v = 0;
        if (kk < NV) {
            int c = kk & 7, m = kk >> 3;
            v = (c * 66 + (h3 + smi[m] - 1) * 6 + (2 * w3 + smj[m] - 1)) * B_TOTAL;
        }
        soff[kk] = v;
    }
    if (t < 8) {
        float s = 0.f;
#pragma unroll
        for (int kk = 0; kk < NV; ++kk) {
            int c = kk & 7, m = kk >> 3;
            s += lcw[(size_t)((t * 8 + c) * 48 + loc) * 4 + smi[m] * 2 + smj[m]] * g_bnB2[c];
        }
        biasc[t] = s;
    }
    __syncthreads();

    const float* gA = g_y2 + B0 + t * 8;
    u64 acc[4][8] = {};
    ulonglong2 f0a, f0b, f1a, f1b;
    { const ulonglong2* p = (const ulonglong2*)(gA + soff[0]); f0a = p[0]; f0b = p[1]; }
    { const ulonglong2* p = (const ulonglong2*)(gA + soff[1]); f1a = p[0]; f1b = p[1]; }

#pragma unroll 4
    for (int k = 0; k < NV; k += 2) {
        LC_BODY(f0a, f0b, k);
        LC_BODY(f1a, f1b, k + 1);
    }

#pragma unroll
    for (int o = 0; o < 8; ++o) {
        const float bv = lcb[o * 48 + loc] + biasc[o];
        float v[8];
#pragma unroll
        for (int p = 0; p < 4; ++p) UNPK(v[2 * p], v[2 * p + 1], acc[p][o]);
#pragma unroll
        for (int p = 0; p < 8; ++p) v[p] = lrelu(v[p] + bv);
        float* dst = g_y3 + ((size_t)o * 48 + loc) * B_TOTAL + B0 + t * 8;
        ((float4*)dst)[0] = make_float4(v[0], v[1], v[2], v[3]);
        ((float4*)dst)[1] = make_float4(v[4], v[5], v[6], v[7]);
        float s = wsum(v[0]+v[1]+v[2]+v[3]+v[4]+v[5]+v[6]+v[7]);
        float q = wsum(v[0]*v[0]+v[1]*v[1]+v[2]*v[2]+v[3]*v[3]
                     + v[4]*v[4]+v[5]*v[5]+v[6]*v[6]+v[7]*v[7]);
        if ((t & 31) == 0) {
            atomicAdd(&red[o * 2 + 0], s);
            atomicAdd(&red[o * 2 + 1], q);
        }
    }
    __syncthreads();
    if (t < 16) g_part3[(by * 48 + loc) * 16 + t] = red[t];
}

__global__ void __launch_bounds__(128, 4) k5_lc3(const float* __restrict__ lcw,
                                                 const float* __restrict__ lcb) {
    __shared__ __align__(16) u64 Wd[256];
    __shared__ float biasc[8];
    __shared__ int soff[34];
    __shared__ float red[16];
    __shared__ int smi[4], smj[4];
    const int t   = threadIdx.x;
    const int loc = blockIdx.x;
    const int B0  = blockIdx.y * 1024;
    const int h3 = loc >> 2, w3 = loc & 3;
    const int nI = (h3 == 0 || h3 == 11) ? 1 : 2;
    const int nJ = (w3 == 0 || w3 == 3) ? 1 : 2;
    const int nIJ = nI * nJ;
    if (nIJ == 4)      k5_body<4>(t, loc, h3, w3, B0, blockIdx.y, lcw, lcb, Wd, biasc, soff, red, smi, smj);
    else if (nIJ == 2) k5_body<2>(t, loc, h3, w3, B0, blockIdx.y, lcw, lcb, Wd, biasc, soff, red, smi, smj);
    else               k5_body<1>(t, loc, h3, w3, B0, blockIdx.y, lcw, lcb, Wd, biasc, soff, red, smi, smj);
}

// ============================ stat reducer ====================================
__global__ void kred(int stage, int nb, int nch, float invN,
                     const float* __restrict__ gamma, const float* __restrict__ beta) {
    __shared__ float sm[1024];
    const float* part = (stage == 0) ? g_part1 : (stage == 1) ? g_part2 : g_part3;
    float* bnA = (stage == 0) ? g_bnA1 : (stage == 1) ? g_bnA2 : g_bnA3;
    float* bnB = (stage == 0) ? g_bnB1 : (stage == 1) ? g_bnB2 : g_bnB3;
    const int t = threadIdx.x;
    const int slots = 2 * nch;
    const int grp = t % slots;
    const int lane = t / slots;
    const int per = blockDim.x / slots;
    float s = 0.f;
    for (int i = lane; i < nb; i += per) s += part[i * slots + grp];
    sm[t] = s;
    __syncthreads();
    for (int step = per >> 1; step > 0; step >>= 1) {
        if (lane < step) sm[t] += sm[t + step * slots];
        __syncthreads();
    }
    if (t < nch) {
        float sum = sm[t * 2 + 0], sq = sm[t * 2 + 1];
        float mean = sum * invN;
        float var = sq * invN - mean * mean;
        float rs = rsqrtf(var + BN_EPS);
        float g = gamma[t];
        bnA[t] = g * rs;
        bnB[t] = beta[t] - mean * g * rs;
    }
}

// ============================ K7: BN3 + transpose to output ===================
__global__ void k7_out(float* __restrict__ out) {
    __shared__ float tile[32][65];
    __shared__ float a3[8], b3[8];
    const int t  = threadIdx.x;
    const int f0 = blockIdx.x * 32;
    const int b0 = blockIdx.y * 64;
    if (t < 8) { a3[t] = g_bnA3[t]; b3[t] = g_bnB3[t]; }
    __syncthreads();
#pragma unroll
    for (int r = 0; r < 8; ++r) {
        int f = r * 4 + (t >> 6);
        int b = t & 63;
        float v = g_y3[(size_t)(f0 + f) * B_TOTAL + b0 + b];
        int c = (f0 + f) / 48;
        tile[f][b] = fmaf(a3[c], v, b3[c]);
    }
    __syncthreads();
#pragma unroll
    for (int r = 0; r < 8; ++r) {
        int f = t & 31;
        int b = r * 8 + (t >> 5);
        out[(size_t)(b0 + b) * 384 + f0 + f] = tile[f][b];
    }
}

// ============================ launch ==========================================
extern "C" void kernel_launch(void* const* d_in, const int* in_sizes, int n_in,
                              void* d_out, int out_size) {
    const float* image = (const float*)d_in[0];
    const float* c1w   = (const float*)d_in[1];
    const float* c1b   = (const float*)d_in[2];
    const float* lc1w  = (const float*)d_in[3];
    const float* lc1b  = (const float*)d_in[4];
    const float* lc2w  = (const float*)d_in[5];
    const float* lc2b  = (const float*)d_in[6];
    const float* lc3w  = (const float*)d_in[7];
    const float* lc3b  = (const float*)d_in[8];
    const float* g1    = (const float*)d_in[9];
    const float* be1   = (const float*)d_in[10];
    const float* g2    = (const float*)d_in[11];
    const float* be2   = (const float*)d_in[12];
    const float* g3    = (const float*)d_in[13];
    const float* be3   = (const float*)d_in[14];
    float* out = (float*)d_out;

    cudaFuncSetAttribute(k0_conv1, cudaFuncAttributeMaxDynamicSharedMemorySize, SMEM0);

    k0_conv1 <<<dim3(32, 8), 256, SMEM0>>>(image, c1w, c1b);
    k1_lc1<0><<<dim3(50, 8), 256>>>(lc1w, lc1b);
    k1_lc1<1><<<dim3(50, 8), 256>>>(lc1w, lc1b);
    kred     <<<1, 1024>>>(0, 400, 16, 1.0f / (8192.0f * 50.0f), g1, be1);
    k3_lc2   <<<dim3(66, 8), 128>>>(lc2w, lc2b);
    kred     <<<1, 1024>>>(1, 528, 8, 1.0f / (8192.0f * 66.0f), g2, be2);
    k5_lc3   <<<dim3(48, 8), 128>>>(lc3w, lc3b);
    kred     <<<1, 1024>>>(2, 384, 8, 1.0f / (8192.0f * 48.0f), g3, be3);
    k7_out   <<<dim3(12, 128), 256>>>(out);
}